// round 11
// baseline (speedup 1.0000x reference)
#include <cuda_runtime.h>
#include <cstdint>

// Problem constants
#define BB   256      // batch
#define TT   512      // timesteps (only last one matters)
#define DIN  64
#define HIDN 64
#define NBAS 10
#define KDIM (DIN*NBAS)   // 640
#define NCLS 2

// Kernel config (R10 base: 2 rows/CTA, 512 threads, 128 CTAs)
#define RPB   2
#define NBLK  (BB/RPB)          // 128 blocks
#define NTHR  512
#define SPLIT 32                // split-k groups
#define KPER  (KDIM/SPLIT)      // 20 k-iters per thread
#define REDW  68                // padded s_red row (conflict-free, 16B-aligned)

__device__ __forceinline__ float fast_tanh(float y) {
    float e = __expf(2.0f * y);
    return 1.0f - __fdividef(2.0f, e + 1.0f);
}
__device__ __forceinline__ float fast_sigmoid(float y) {
    return __fdividef(1.0f, 1.0f + __expf(-y));
}

// packed helpers (sm_100a f32x2 pipe)
__device__ __forceinline__ unsigned long long pack_dup(float p) {
    unsigned long long r;
    asm("mov.b64 %0, {%1, %1};" : "=l"(r) : "r"(__float_as_uint(p)));
    return r;
}
__device__ __forceinline__ void fma2(unsigned long long& d,
                                     unsigned long long a,
                                     unsigned long long b) {
    asm("fma.rn.f32x2 %0, %1, %2, %0;" : "+l"(d) : "l"(a), "l"(b));
}

__global__ __launch_bounds__(NTHR) void node_rnn_fused_kernel(
    const float* __restrict__ x,
    const float* __restrict__ c0, const float* __restrict__ w0, const float* __restrict__ C0,
    const float* __restrict__ c1, const float* __restrict__ w1, const float* __restrict__ C1,
    const float* __restrict__ c2, const float* __restrict__ w2, const float* __restrict__ C2,
    const float* __restrict__ Whead, const float* __restrict__ bhead,
    float* __restrict__ out)
{
    __shared__ float s_x  [RPB][DIN];
    __shared__ float s_val[RPB][HIDN];
    __shared__ float s_phi[RPB][KDIM];
    __shared__ float s_red[SPLIT][RPB][REDW];
    __shared__ float s_c[3][NBAS], s_iw[3][NBAS];
    __shared__ float s_W[HIDN * NCLS];
    __shared__ float s_b[NCLS];

    const int tid = threadIdx.x;
    const int r0  = blockIdx.x * RPB;

    // --- startup loads (independent, high MLP) ---
    if (tid < NBAS)        { s_c[0][tid]      = c0[tid];      s_iw[0][tid]      = __frcp_rn(w0[tid]); }
    else if (tid < 2*NBAS) { int k = tid-NBAS;   s_c[1][k] = c1[k]; s_iw[1][k] = __frcp_rn(w1[k]); }
    else if (tid < 3*NBAS) { int k = tid-2*NBAS; s_c[2][k] = c2[k]; s_iw[2][k] = __frcp_rn(w2[k]); }

    if (tid >= 128 && tid < 128 + HIDN * NCLS) s_W[tid - 128] = Whead[tid - 128];
    if (tid >= 384 && tid < 384 + NCLS)        s_b[tid - 384] = bhead[tid - 384];

    if (tid >= 256 && tid < 256 + RPB * DIN) {
        int t = tid - 256;
        int r = t >> 6, i = t & 63;
        s_x[r][i] = x[(size_t)(r0 + r) * (TT * DIN) + (size_t)(TT - 1) * DIN + i];
    }

    // GEMM mapping
    const int q   = tid & 15;        // output quad: columns 4q..4q+3
    const int g   = tid >> 4;        // split-k group 0..31
    const int kk0 = g * KPER;

    // warp-local reduce mapping: warp w reduces (r,u) pairs for units 4w..4w+3
    const int wid  = tid >> 5;
    const int lane = tid & 31;
    const int part = lane & 3;
    const int idx  = lane >> 2;      // 0..7
    const int rr   = idx >> 2;       // row 0..1
    const int uu   = (wid << 2) + (idx & 3);   // hidden unit 0..63
    const int kbeg = (part < 2) ? part * 3 : 6 + (part - 2) * 2;  // {0,3,6,8}
    const int kcnt = (part < 2) ? 3 : 2;

    const float* Cs[3] = { C0, C1, C2 };

    // ---- stage-0 coefficient loads (front-batched, whole stage; packed pairs) ----
    ulonglong2 cv[KPER];
    #pragma unroll
    for (int j = 0; j < KPER; ++j)
        cv[j] = *reinterpret_cast<const ulonglong2*>(C0 + (size_t)(kk0 + j) * HIDN + 4 * q);

    __syncthreads();   // consts + x rows ready

    // ---- stage-0 phi from x, spread across ALL threads ----
    #pragma unroll
    for (int it = tid; it < RPB * KDIM; it += NTHR) {
        int r = it / KDIM, rem = it - r * KDIM;
        int i = rem / NBAS, k = rem - i * NBAS;
        s_phi[r][rem] = fast_tanh((s_x[r][i] - s_c[0][k]) * s_iw[0][k]);
    }
    __syncthreads();

    #pragma unroll 1
    for (int stage = 0; stage < 3; ++stage) {
        // ---- split-k GEMM: packed f32x2 FMA, coeffs in regs, phi from smem ----
        unsigned long long A00 = 0ull, A01 = 0ull;   // row 0: cols (4q,4q+1),(4q+2,4q+3)
        unsigned long long A10 = 0ull, A11 = 0ull;   // row 1

        #pragma unroll
        for (int jj = 0; jj < KPER / 4; ++jj) {
            float4 p0 = *reinterpret_cast<const float4*>(&s_phi[0][kk0 + 4 * jj]);
            float4 p1 = *reinterpret_cast<const float4*>(&s_phi[1][kk0 + 4 * jj]);
            #pragma unroll
            for (int e = 0; e < 4; ++e) {
                ulonglong2 c2p = cv[4 * jj + e];
                float pa = (e == 0) ? p0.x : (e == 1) ? p0.y : (e == 2) ? p0.z : p0.w;
                float pb = (e == 0) ? p1.x : (e == 1) ? p1.y : (e == 2) ? p1.z : p1.w;
                unsigned long long paa = pack_dup(pa);
                unsigned long long pbb = pack_dup(pb);
                fma2(A00, c2p.x, paa);
                fma2(A01, c2p.y, paa);
                fma2(A10, c2p.x, pbb);
                fma2(A11, c2p.y, pbb);
            }
        }

        // ---- prefetch NEXT stage's coefficients (cv regs now dead) ----
        if (stage < 2) {
            const float* __restrict__ Cn = Cs[stage + 1];
            #pragma unroll
            for (int j = 0; j < KPER; ++j)
                cv[j] = *reinterpret_cast<const ulonglong2*>(Cn + (size_t)(kk0 + j) * HIDN + 4 * q);
        }

        // ---- write partials (packed 16B stores, no unpack) ----
        *reinterpret_cast<ulonglong2*>(&s_red[g][0][4 * q]) = make_ulonglong2(A00, A01);
        *reinterpret_cast<ulonglong2*>(&s_red[g][1][4 * q]) = make_ulonglong2(A10, A11);
        __syncthreads();

        // ---- fused: warp-local reduce + activation + next-stage phi ----
        {
            float v = 0.0f;
            #pragma unroll
            for (int jj = 0; jj < 8; ++jj)
                v += s_red[part + 4 * jj][rr][uu];
            v += __shfl_xor_sync(0xffffffffu, v, 1);
            v += __shfl_xor_sync(0xffffffffu, v, 2);   // all 4 group threads hold the sum

            float h = (stage == 0) ? v : fast_sigmoid(v);

            if (stage < 2) {
                const int st = stage + 1;
                #pragma unroll
                for (int t = 0; t < 3; ++t) {
                    if (t < kcnt) {
                        int k = kbeg + t;
                        s_phi[rr][uu * NBAS + k] =
                            fast_tanh((h - s_c[st][k]) * s_iw[st][k]);
                    }
                }
            } else {
                if (part == 0) s_val[rr][uu] = h;
            }
        }
        __syncthreads();
    }

    // ---- head: logits[r][c] = h . W[:,c] + b[c] ----
    if (tid < RPB * NCLS) {
        int r = tid / NCLS, c = tid % NCLS;
        float s = s_b[c];
        #pragma unroll
        for (int o = 0; o < HIDN; ++o)
            s = fmaf(s_val[r][o], s_W[o * NCLS + c], s);
        out[(r0 + r) * NCLS + c] = s;
    }
}

extern "C" void kernel_launch(void* const* d_in, const int* in_sizes, int n_in,
                              void* d_out, int out_size) {
    (void)in_sizes; (void)n_in; (void)out_size;
    const float* x  = (const float*)d_in[0];
    const float* c0 = (const float*)d_in[1];
    const float* w0 = (const float*)d_in[2];
    const float* C0 = (const float*)d_in[3];
    const float* c1 = (const float*)d_in[4];
    const float* w1 = (const float*)d_in[5];
    const float* C1 = (const float*)d_in[6];
    const float* c2 = (const float*)d_in[7];
    const float* w2 = (const float*)d_in[8];
    const float* C2 = (const float*)d_in[9];
    const float* W  = (const float*)d_in[10];
    const float* b  = (const float*)d_in[11];
    float* out = (float*)d_out;

    node_rnn_fused_kernel<<<NBLK, NTHR>>>(x, c0, w0, C0, c1, w1, C1,
                                          c2, w2, C2, W, b, out);
}

// round 13
// speedup vs baseline: 1.0028x; 1.0028x over previous
#include <cuda_runtime.h>
#include <cstdint>

// Problem constants
#define BB   256      // batch
#define TT   512      // timesteps (only last one matters)
#define DIN  64
#define HIDN 64
#define NBAS 10
#define KDIM (DIN*NBAS)   // 640
#define NCLS 2

// Kernel config (R10 base: 2 rows/CTA, 512 threads, 128 CTAs)
#define RPB   2
#define NBLK  (BB/RPB)          // 128 blocks
#define NTHR  512
#define SPLIT 32                // split-k groups
#define KPER  (KDIM/SPLIT)      // 20 k-iters per thread
#define REDW  68                // padded s_red row (conflict-free, 16B-aligned)

__device__ __forceinline__ float fast_tanh(float y) {
    float e = __expf(2.0f * y);
    return 1.0f - __fdividef(2.0f, e + 1.0f);
}
__device__ __forceinline__ float fast_sigmoid(float y) {
    return __fdividef(1.0f, 1.0f + __expf(-y));
}

// packed helpers (sm_100a f32x2 pipe)
__device__ __forceinline__ unsigned long long pack_dup(float p) {
    unsigned long long r;
    asm("mov.b64 %0, {%1, %1};" : "=l"(r) : "r"(__float_as_uint(p)));
    return r;
}
__device__ __forceinline__ void fma2(unsigned long long& d,
                                     unsigned long long a,
                                     unsigned long long b) {
    asm("fma.rn.f32x2 %0, %1, %2, %0;" : "+l"(d) : "l"(a), "l"(b));
}

__global__ __launch_bounds__(NTHR) void node_rnn_fused_kernel(
    const float* __restrict__ x,
    const float* __restrict__ c0, const float* __restrict__ w0, const float* __restrict__ C0,
    const float* __restrict__ c1, const float* __restrict__ w1, const float* __restrict__ C1,
    const float* __restrict__ c2, const float* __restrict__ w2, const float* __restrict__ C2,
    const float* __restrict__ Whead, const float* __restrict__ bhead,
    float* __restrict__ out)
{
    __shared__ float s_x  [RPB][DIN];
    __shared__ float s_val[RPB][HIDN];
    __shared__ float s_phi[RPB][KDIM];
    __shared__ float s_red[SPLIT][RPB][REDW];
    __shared__ float s_c[3][NBAS], s_iw[3][NBAS];
    __shared__ float s_W[HIDN * NCLS];
    __shared__ float s_b[NCLS];

    const int tid = threadIdx.x;
    const int r0  = blockIdx.x * RPB;

    // --- startup loads (independent, high MLP) ---
    if (tid < NBAS)        { s_c[0][tid]      = c0[tid];      s_iw[0][tid]      = __frcp_rn(w0[tid]); }
    else if (tid < 2*NBAS) { int k = tid-NBAS;   s_c[1][k] = c1[k]; s_iw[1][k] = __frcp_rn(w1[k]); }
    else if (tid < 3*NBAS) { int k = tid-2*NBAS; s_c[2][k] = c2[k]; s_iw[2][k] = __frcp_rn(w2[k]); }

    if (tid >= 128 && tid < 128 + HIDN * NCLS) s_W[tid - 128] = Whead[tid - 128];
    if (tid >= 384 && tid < 384 + NCLS)        s_b[tid - 384] = bhead[tid - 384];

    if (tid >= 256 && tid < 256 + RPB * DIN) {
        int t = tid - 256;
        int r = t >> 6, i = t & 63;
        s_x[r][i] = x[(size_t)(r0 + r) * (TT * DIN) + (size_t)(TT - 1) * DIN + i];
    }

    // GEMM mapping
    const int q   = tid & 15;        // output quad: columns 4q..4q+3
    const int g   = tid >> 4;        // split-k group 0..31
    const int kk0 = g * KPER;

    // warp-local reduce mapping: warp w reduces (r,u) pairs for units 4w..4w+3
    const int wid  = tid >> 5;
    const int lane = tid & 31;
    const int part = lane & 3;
    const int idx  = lane >> 2;      // 0..7
    const int rr   = idx >> 2;       // row 0..1
    const int uu   = (wid << 2) + (idx & 3);   // hidden unit 0..63
    const int kbeg = (part < 2) ? part * 3 : 6 + (part - 2) * 2;  // {0,3,6,8}
    const int kcnt = (part < 2) ? 3 : 2;

    const float* Cs[3] = { C0, C1, C2 };

    // ---- stage-0 coefficient loads (front-batched, whole stage; packed pairs) ----
    ulonglong2 cv[KPER];
    #pragma unroll
    for (int j = 0; j < KPER; ++j)
        cv[j] = *reinterpret_cast<const ulonglong2*>(C0 + (size_t)(kk0 + j) * HIDN + 4 * q);

    __syncthreads();   // consts + x rows ready

    // ---- stage-0 phi from x, spread across ALL threads ----
    #pragma unroll
    for (int it = tid; it < RPB * KDIM; it += NTHR) {
        int r = it / KDIM, rem = it - r * KDIM;
        int i = rem / NBAS, k = rem - i * NBAS;
        s_phi[r][rem] = fast_tanh((s_x[r][i] - s_c[0][k]) * s_iw[0][k]);
    }
    __syncthreads();

    #pragma unroll 1
    for (int stage = 0; stage < 3; ++stage) {
        // ---- split-k GEMM: packed f32x2 FMA, coeffs in regs, phi from smem ----
        unsigned long long A00 = 0ull, A01 = 0ull;   // row 0: cols (4q,4q+1),(4q+2,4q+3)
        unsigned long long A10 = 0ull, A11 = 0ull;   // row 1

        #pragma unroll
        for (int jj = 0; jj < KPER / 4; ++jj) {
            float4 p0 = *reinterpret_cast<const float4*>(&s_phi[0][kk0 + 4 * jj]);
            float4 p1 = *reinterpret_cast<const float4*>(&s_phi[1][kk0 + 4 * jj]);
            #pragma unroll
            for (int e = 0; e < 4; ++e) {
                ulonglong2 c2p = cv[4 * jj + e];
                float pa = (e == 0) ? p0.x : (e == 1) ? p0.y : (e == 2) ? p0.z : p0.w;
                float pb = (e == 0) ? p1.x : (e == 1) ? p1.y : (e == 2) ? p1.z : p1.w;
                unsigned long long paa = pack_dup(pa);
                unsigned long long pbb = pack_dup(pb);
                fma2(A00, c2p.x, paa);
                fma2(A01, c2p.y, paa);
                fma2(A10, c2p.x, pbb);
                fma2(A11, c2p.y, pbb);
            }
        }

        // ---- prefetch NEXT stage's coefficients (cv regs now dead) ----
        if (stage < 2) {
            const float* __restrict__ Cn = Cs[stage + 1];
            #pragma unroll
            for (int j = 0; j < KPER; ++j)
                cv[j] = *reinterpret_cast<const ulonglong2*>(Cn + (size_t)(kk0 + j) * HIDN + 4 * q);
        }

        // ---- write partials (packed 16B stores, no unpack) ----
        *reinterpret_cast<ulonglong2*>(&s_red[g][0][4 * q]) = make_ulonglong2(A00, A01);
        *reinterpret_cast<ulonglong2*>(&s_red[g][1][4 * q]) = make_ulonglong2(A10, A11);
        __syncthreads();

        // ---- fused: warp-local reduce + activation + next-stage phi ----
        {
            float v = 0.0f;
            #pragma unroll
            for (int jj = 0; jj < 8; ++jj)
                v += s_red[part + 4 * jj][rr][uu];
            v += __shfl_xor_sync(0xffffffffu, v, 1);
            v += __shfl_xor_sync(0xffffffffu, v, 2);   // all 4 group threads hold the sum

            float h = (stage == 0) ? v : fast_sigmoid(v);

            if (stage < 2) {
                const int st = stage + 1;
                #pragma unroll
                for (int t = 0; t < 3; ++t) {
                    if (t < kcnt) {
                        int k = kbeg + t;
                        s_phi[rr][uu * NBAS + k] =
                            fast_tanh((h - s_c[st][k]) * s_iw[st][k]);
                    }
                }
            } else {
                if (part == 0) s_val[rr][uu] = h;
            }
        }
        __syncthreads();
    }

    // ---- head: logits[r][c] = h . W[:,c] + b[c] ----
    if (tid < RPB * NCLS) {
        int r = tid / NCLS, c = tid % NCLS;
        float s = s_b[c];
        #pragma unroll
        for (int o = 0; o < HIDN; ++o)
            s = fmaf(s_val[r][o], s_W[o * NCLS + c], s);
        out[(r0 + r) * NCLS + c] = s;
    }
}

extern "C" void kernel_launch(void* const* d_in, const int* in_sizes, int n_in,
                              void* d_out, int out_size) {
    (void)in_sizes; (void)n_in; (void)out_size;
    const float* x  = (const float*)d_in[0];
    const float* c0 = (const float*)d_in[1];
    const float* w0 = (const float*)d_in[2];
    const float* C0 = (const float*)d_in[3];
    const float* c1 = (const float*)d_in[4];
    const float* w1 = (const float*)d_in[5];
    const float* C1 = (const float*)d_in[6];
    const float* c2 = (const float*)d_in[7];
    const float* w2 = (const float*)d_in[8];
    const float* C2 = (const float*)d_in[9];
    const float* W  = (const float*)d_in[10];
    const float* b  = (const float*)d_in[11];
    float* out = (float*)d_out;

    node_rnn_fused_kernel<<<NBLK, NTHR>>>(x, c0, w0, C0, c1, w1, C1,
                                          c2, w2, C2, W, b, out);
}